// round 14
// baseline (speedup 1.0000x reference)
#include <cuda_runtime.h>
#include <cuda_fp16.h>
#include <cstdint>

#define BATCH 8192
#define OUTF  4096
#define INF   4096
#define PACKED_LEN 512

// ---------------- GEMM tiling ----------------
#define TM 128
#define TN 64
#define KS 128                       // fp8 K elements per stage (128 B rows)
#define NK (INF / KS)                // 32 K-iterations
#define STAGES 3
#define THREADS 256

// Persistent grid: 152 SMs x 3 CTAs. Bids [304,456) -> popc role (exactly 1/SM).
#define GRID_P    456
#define QMMA_CTAS 304

// Column partition of the 64x64 tile grid:
//   QMMA pool: ntile in [0,34)  -> 64*34 = 2176 tiles
//   POPC pool: ntile in [34,64) -> 64*30 = 1920 tiles (47%, capacity-balanced)
#define NQCOL 34
#define NPCOL 30
#define NQT (64 * NQCOL)
#define NPT (64 * NPCOL)

#define A_TILE_BYTES (TM * 128)          // 16 KB
#define B_TILE_BYTES (TN * 128)          // 8 KB
#define STAGE_BYTES (A_TILE_BYTES + B_TILE_BYTES)  // 24 KB
#define SMEM_DYN (STAGES * STAGE_BYTES + 1024)     // ~73 KB -> 3 CTAs/SM

// Scratch (no cudaMalloc allowed -> __device__ globals)
__device__ __align__(16) uint8_t  g_A[(size_t)BATCH * INF];        // fp8, 32 MB
__device__ __align__(16) uint8_t  g_W[(size_t)OUTF * INF];         // fp8, 16 MB
__device__ __align__(16) uint32_t g_Ap[(size_t)BATCH * (INF/32)];  // packed, 4 MB
__device__ __align__(16) uint32_t g_Wp[(size_t)OUTF * (INF/32)];   // packed, 2 MB
__device__ int g_ctr_q;   // QMMA work queue head (zeroed by unpack kernel)
__device__ int g_ctr_p;   // POPC work queue head

// ---------------- helpers ----------------
__device__ __forceinline__ uint32_t smem_u32(const void* p) {
    return (uint32_t)__cvta_generic_to_shared(p);
}
__device__ __forceinline__ void cp_async16(uint32_t sdst, const void* gsrc) {
    asm volatile("cp.async.cg.shared.global [%0], [%1], 16;" :: "r"(sdst), "l"(gsrc));
}
__device__ __forceinline__ void cp_commit() {
    asm volatile("cp.async.commit_group;");
}
template <int N>
__device__ __forceinline__ void cp_wait() {
    asm volatile("cp.async.wait_group %0;" :: "n"(N));
}
__device__ __forceinline__ void ldsm_x4(uint32_t* r, uint32_t addr) {
    asm volatile("ldmatrix.sync.aligned.m8n8.x4.shared.b16 {%0,%1,%2,%3}, [%4];"
                 : "=r"(r[0]), "=r"(r[1]), "=r"(r[2]), "=r"(r[3]) : "r"(addr));
}
// FP8 e5m2 x e5m2 -> f16 accumulator (exact: acc is an even integer <= 4096)
__device__ __forceinline__ void qmma_f16(uint32_t* c, const uint32_t* a,
                                         uint32_t b0, uint32_t b1) {
    asm volatile(
        "mma.sync.aligned.m16n8k32.row.col.f16.e5m2.e5m2.f16 "
        "{%0,%1}, {%2,%3,%4,%5}, {%6,%7}, {%0,%1};"
        : "+r"(c[0]), "+r"(c[1])
        : "r"(a[0]), "r"(a[1]), "r"(a[2]), "r"(a[3]), "r"(b0), "r"(b1));
}

// ---------------- Unpack: 8 bits (LSB-first) -> 8 e5m2 (+/-1) + dense bit-pack ----
__device__ __forceinline__ uint2 unpack8(unsigned v) {
    uint2 r;
    r.x = 0xBCBCBCBCu ^ (((v >> 0) & 1u) << 7)
                      ^ (((v >> 1) & 1u) << 15)
                      ^ (((v >> 2) & 1u) << 23)
                      ^ (((v >> 3) & 1u) << 31);
    r.y = 0xBCBCBCBCu ^ (((v >> 4) & 1u) << 7)
                      ^ (((v >> 5) & 1u) << 15)
                      ^ (((v >> 6) & 1u) << 23)
                      ^ (((v >> 7) & 1u) << 31);
    return r;
}

#define NA4 (BATCH * PACKED_LEN / 4)   // 1048576
#define NW4 (OUTF * PACKED_LEN / 4)    // 524288
__global__ void unpack_all_kernel(const int* __restrict__ pa,
                                  const int* __restrict__ pw) {
    int i = blockIdx.x * blockDim.x + threadIdx.x;
    if (i == 0) { g_ctr_q = 0; g_ctr_p = 0; }   // reset work queues each launch
    const int* src;
    uint4* dstf;
    uint32_t* dstp;
    int idx;
    if (i < NA4) { src = pa; dstf = (uint4*)g_A; dstp = g_Ap; idx = i; }
    else if (i < NA4 + NW4) { src = pw; dstf = (uint4*)g_W; dstp = g_Wp; idx = i - NA4; }
    else return;
    int4 p = ((const int4*)src)[idx];
    uint2 l0 = unpack8((unsigned)p.x);
    uint2 l1 = unpack8((unsigned)p.y);
    uint2 l2 = unpack8((unsigned)p.z);
    uint2 l3 = unpack8((unsigned)p.w);
    dstf[2 * idx]     = make_uint4(l0.x, l0.y, l1.x, l1.y);
    dstf[2 * idx + 1] = make_uint4(l2.x, l2.y, l3.x, l3.y);
    dstp[idx] = ((unsigned)p.x & 0xFFu)
              | (((unsigned)p.y & 0xFFu) << 8)
              | (((unsigned)p.z & 0xFFu) << 16)
              | (((unsigned)p.w & 0xFFu) << 24);
}

// ---------------- POPC tile: 128x64, K=4096 packed ----------------
__device__ __forceinline__ void popc_tile(char* smem, int tid, int mtile, int ntile,
                                          const float* __restrict__ bias,
                                          float* __restrict__ out) {
    uint32_t* As = (uint32_t*)smem;         // [64 kw][128 rows] = 32 KB
    uint32_t* Ws = As + 64 * 128;           // [64 kw][64 cols]  = 16 KB

    const int rg  = tid & 15;               // -> rows rg*8 .. rg*8+7
    const int cg4 = (tid >> 4) * 4;         // -> cols cg4 .. cg4+3

    int acc[8][4];
#pragma unroll
    for (int r = 0; r < 8; ++r)
#pragma unroll
        for (int c = 0; c < 4; ++c) acc[r][c] = 0;

    const int arow  = tid & 127;
    const int ahalf = tid >> 7;
    const int wrow  = tid & 63;
    const int wq    = tid >> 6;

#pragma unroll 1
    for (int ch = 0; ch < 2; ++ch) {
        {
            const uint4* asrc = (const uint4*)(g_Ap
                + (size_t)(mtile * TM + arow) * 128 + ch * 64 + ahalf * 32);
#pragma unroll
            for (int i = 0; i < 8; ++i) {
                uint4 v = asrc[i];
                int kwl = ahalf * 32 + i * 4;
                As[(kwl + 0) * 128 + arow] = v.x;
                As[(kwl + 1) * 128 + arow] = v.y;
                As[(kwl + 2) * 128 + arow] = v.z;
                As[(kwl + 3) * 128 + arow] = v.w;
            }
            const uint4* wsrc = (const uint4*)(g_Wp
                + (size_t)(ntile * TN + wrow) * 128 + ch * 64 + wq * 16);
#pragma unroll
            for (int i = 0; i < 4; ++i) {
                uint4 v = wsrc[i];
                int kwl = wq * 16 + i * 4;
                Ws[(kwl + 0) * 64 + wrow] = v.x;
                Ws[(kwl + 1) * 64 + wrow] = v.y;
                Ws[(kwl + 2) * 64 + wrow] = v.z;
                Ws[(kwl + 3) * 64 + wrow] = v.w;
            }
        }
        __syncthreads();

#pragma unroll 2
        for (int kw = 0; kw < 64; ++kw) {
            const uint4* As4 = (const uint4*)(As + kw * 128 + rg * 8);
            uint4 a0 = As4[0];
            uint4 a1 = As4[1];
            uint4 w  = *(const uint4*)(Ws + kw * 64 + cg4);
            uint32_t av[8] = {a0.x, a0.y, a0.z, a0.w, a1.x, a1.y, a1.z, a1.w};
            uint32_t wv[4] = {w.x, w.y, w.z, w.w};
#pragma unroll
            for (int r = 0; r < 8; ++r)
#pragma unroll
                for (int c = 0; c < 4; ++c)
                    acc[r][c] += __popc(av[r] ^ wv[c]);
        }
        __syncthreads();
    }

    const int colbase = ntile * TN + cg4;
    float b0 = __ldg(bias + colbase + 0);
    float b1 = __ldg(bias + colbase + 1);
    float b2 = __ldg(bias + colbase + 2);
    float b3 = __ldg(bias + colbase + 3);
#pragma unroll
    for (int r = 0; r < 8; ++r) {
        int row = mtile * TM + rg * 8 + r;
        float4 o;
        o.x = (float)(4096 - 2 * acc[r][0]) + b0;
        o.y = (float)(4096 - 2 * acc[r][1]) + b1;
        o.z = (float)(4096 - 2 * acc[r][2]) + b2;
        o.w = (float)(4096 - 2 * acc[r][3]) + b3;
        *(float4*)(void*)(out + (size_t)row * OUTF + colbase) = o;
    }
}

// ---------------- QMMA tile: 128x64, K=4096 fp8 ----------------
__device__ __forceinline__ void qmma_tile(char* smem, int tid, int mtile, int ntile,
                                          const float* __restrict__ bias,
                                          float* __restrict__ out) {
    const uint32_t sbase = smem_u32(smem);
    const int wid  = tid >> 5;
    const int lane = tid & 31;
    const int warp_m = wid & 3;
    const int warp_n = wid >> 2;

    const uint8_t* __restrict__ Ag0 = g_A + (size_t)(mtile * TM) * INF;
    const uint8_t* __restrict__ Wg0 = g_W + (size_t)(ntile * TN) * INF;

    const int tr = tid >> 3;
    const int tc = tid & 7;
    const uint8_t* pf_gA = Ag0 + (size_t)tr * INF + tc * 16;
    const uint8_t* pf_gW = Wg0 + (size_t)tr * INF + tc * 16;
    const uint32_t pf_s  = tr * 128 + ((tc ^ (tr & 7)) << 4);

    auto prefetch = [&](int kt) {
        const uint32_t sst = sbase + (kt % STAGES) * STAGE_BYTES;
        const uint8_t* ga = pf_gA + kt * KS;
        const uint8_t* gw = pf_gW + kt * KS;
#pragma unroll
        for (int it = 0; it < 4; ++it)
            cp_async16(sst + pf_s + it * (32 * 128), ga + (size_t)it * (32 * INF));
#pragma unroll
        for (int it = 0; it < 2; ++it)
            cp_async16(sst + A_TILE_BYTES + pf_s + it * (32 * 128),
                       gw + (size_t)it * (32 * INF));
        cp_commit();
    };

    const int j = lane >> 3;
    const int arow_in = (lane & 7) + ((j & 1) << 3);
    const int achk    = j >> 1;
    const int brow_in = (lane & 7) + ((j >> 1) << 3);
    const int bchk    = j & 1;

    uint32_t offA[2][4];
    uint32_t offB[2][4];
#pragma unroll
    for (int mf = 0; mf < 2; ++mf) {
        int row = warp_m * 32 + mf * 16 + arow_in;
#pragma unroll
        for (int ks = 0; ks < 4; ++ks)
            offA[mf][ks] = row * 128 + (((ks * 2 + achk) ^ (row & 7)) << 4);
    }
#pragma unroll
    for (int nb = 0; nb < 2; ++nb) {
        int row = warp_n * 32 + nb * 16 + brow_in;
#pragma unroll
        for (int ks = 0; ks < 4; ++ks)
            offB[nb][ks] = A_TILE_BYTES + row * 128 +
                           (((ks * 2 + bchk) ^ (row & 7)) << 4);
    }

    uint32_t c_acc[2][4][2];
#pragma unroll
    for (int mf = 0; mf < 2; ++mf)
#pragma unroll
        for (int nf = 0; nf < 4; ++nf) {
            c_acc[mf][nf][0] = 0u;
            c_acc[mf][nf][1] = 0u;
        }

    prefetch(0);
    prefetch(1);
    cp_wait<1>();
    __syncthreads();

    for (int kt = 0; kt < NK; ++kt) {
        const uint32_t sa = sbase + (kt % STAGES) * STAGE_BYTES;
        const bool notlast = (kt + 1 < NK);

#pragma unroll
        for (int ks = 0; ks < 4; ++ks) {
            uint32_t a[2][4], b[2][4];
#pragma unroll
            for (int mf = 0; mf < 2; ++mf) ldsm_x4(a[mf], sa + offA[mf][ks]);
#pragma unroll
            for (int nb = 0; nb < 2; ++nb) ldsm_x4(b[nb], sa + offB[nb][ks]);
#pragma unroll
            for (int mf = 0; mf < 2; ++mf)
#pragma unroll
                for (int nf = 0; nf < 4; ++nf)
                    qmma_f16(c_acc[mf][nf], a[mf],
                             b[nf >> 1][(nf & 1) * 2],
                             b[nf >> 1][(nf & 1) * 2 + 1]);

            if (ks == 2 && notlast) {
                cp_wait<0>();     // drain all groups; tile ends with queue empty
                __syncthreads();
                if (kt + 2 < NK) prefetch(kt + 2);
            }
        }
    }

    const int gid = lane >> 2;
    const int tig = lane & 3;
#pragma unroll
    for (int mf = 0; mf < 2; ++mf) {
        int r0 = mtile * TM + warp_m * 32 + mf * 16 + gid;
#pragma unroll
        for (int nf = 0; nf < 4; ++nf) {
            int col = ntile * TN + warp_n * 32 + nf * 8 + 2 * tig;
            float bx = __ldg(bias + col);
            float by = __ldg(bias + col + 1);
            half2 h0 = *(half2*)&c_acc[mf][nf][0];
            half2 h1 = *(half2*)&c_acc[mf][nf][1];
            float2 f0 = __half22float2(h0);
            float2 f1 = __half22float2(h1);
            float2 v0, v1;
            v0.x = f0.x + bx;  v0.y = f0.y + by;
            v1.x = f1.x + bx;  v1.y = f1.y + by;
            *(float2*)(void*)(out + (size_t)r0 * OUTF + col) = v0;
            *(float2*)(void*)(out + (size_t)(r0 + 8) * OUTF + col) = v1;
        }
    }
}

// ---------------- Persistent hybrid GEMM: role-pinned CTAs + work queues ------
__global__ __launch_bounds__(THREADS, 3)
void bitlinear_gemm(const float* __restrict__ bias, float* __restrict__ out) {
    extern __shared__ char smem_raw[];
    char* smem = (char*)(((uintptr_t)smem_raw + 1023) & ~(uintptr_t)1023);
    __shared__ int s_work;

    const int tid = threadIdx.x;
    // Wave-1 placement: each SM hosts one bid from [0,152),[152,304),[304,456).
    // bid >= 304 -> popc role: exactly ONE popc CTA per SM, always.
    const bool prefer_popc = (blockIdx.x >= QMMA_CTAS);

    for (;;) {
        if (tid == 0) {
            int id;
            if (prefer_popc) {
                id = atomicAdd(&g_ctr_p, 1);
                if (id < NPT) id += NQT;
                else {
                    id = atomicAdd(&g_ctr_q, 1);      // steal from QMMA pool
                    if (id >= NQT) id = -1;
                }
            } else {
                id = atomicAdd(&g_ctr_q, 1);
                if (id >= NQT) {
                    int p = atomicAdd(&g_ctr_p, 1);    // steal from popc pool
                    id = (p < NPT) ? NQT + p : -1;
                }
            }
            s_work = id;
        }
        __syncthreads();           // publishes s_work; also fences prior tile's smem reads
        const int work = s_work;
        if (work < 0) return;

        if (work >= NQT) {
            const int p = work - NQT;
            popc_tile(smem, tid, p / NPCOL, NQCOL + p % NPCOL, bias, out);
        } else {
            qmma_tile(smem, tid, work / NQCOL, work % NQCOL, bias, out);
        }
        // Both tile paths contain >= 1 internal __syncthreads after the `work`
        // read, so thread 0's next s_work write cannot race the read above.
    }
}

// ---------------- launch ----------------
extern "C" void kernel_launch(void* const* d_in, const int* in_sizes, int n_in,
                              void* d_out, int out_size) {
    const int*   inp  = (const int*)d_in[0];   // [8192, 512] int32 (low 8 bits)
    const int*   wp   = (const int*)d_in[1];   // [4096, 512] int32
    const float* bias = (const float*)d_in[2]; // [4096]
    float*       out  = (float*)d_out;         // [8192, 4096] fp32

    cudaFuncSetAttribute(bitlinear_gemm,
                         cudaFuncAttributeMaxDynamicSharedMemorySize, SMEM_DYN);

    const int nTot = NA4 + NW4;  // 1572864
    unpack_all_kernel<<<(nTot + 255) / 256, 256>>>(inp, wp);

    bitlinear_gemm<<<GRID_P, THREADS, SMEM_DYN>>>(bias, out);
}

// round 15
// speedup vs baseline: 1.0800x; 1.0800x over previous
#include <cuda_runtime.h>
#include <cuda_fp16.h>
#include <cstdint>

#define BATCH 8192
#define OUTF  4096
#define INF   4096
#define PACKED_LEN 512

// ---------------- GEMM tiling ----------------
#define TM 128
#define TN 64
#define KS 128                       // fp8 K elements per stage (128 B rows)
#define NK (INF / KS)                // 32 K-iterations
#define STAGES 3
#define THREADS 256

// Per 8 consecutive bids: 7 QMMA CTAs + 1 POPC CTA (uniform interleave, f=12.5%).
// popc g -> (mtile=g>>3, ntile=56+(g&7)); qmma q=7g+s -> (q/56, q%56).
#define NPOPC 8
#define NQ    (64 - NPOPC)

#define A_TILE_BYTES (TM * 128)          // 16 KB
#define B_TILE_BYTES (TN * 128)          // 8 KB
#define STAGE_BYTES (A_TILE_BYTES + B_TILE_BYTES)  // 24 KB
#define SMEM_DYN (STAGES * STAGE_BYTES + 1024)     // ~73 KB -> 3 CTAs/SM

// Scratch (no cudaMalloc allowed -> __device__ globals)
__device__ __align__(16) uint8_t  g_A[(size_t)BATCH * INF];        // fp8, 32 MB
__device__ __align__(16) uint8_t  g_W[(size_t)OUTF * INF];         // fp8, 16 MB
__device__ __align__(16) uint32_t g_Ap[(size_t)BATCH * (INF/32)];  // packed, 4 MB
__device__ __align__(16) uint32_t g_Wp[(size_t)OUTF * (INF/32)];   // packed, 2 MB

// ---------------- helpers ----------------
__device__ __forceinline__ uint32_t smem_u32(const void* p) {
    return (uint32_t)__cvta_generic_to_shared(p);
}
__device__ __forceinline__ void cp_async16(uint32_t sdst, const void* gsrc) {
    asm volatile("cp.async.cg.shared.global [%0], [%1], 16;" :: "r"(sdst), "l"(gsrc));
}
__device__ __forceinline__ void cp_commit() {
    asm volatile("cp.async.commit_group;");
}
template <int N>
__device__ __forceinline__ void cp_wait() {
    asm volatile("cp.async.wait_group %0;" :: "n"(N));
}
__device__ __forceinline__ void ldsm_x4(uint32_t* r, uint32_t addr) {
    asm volatile("ldmatrix.sync.aligned.m8n8.x4.shared.b16 {%0,%1,%2,%3}, [%4];"
                 : "=r"(r[0]), "=r"(r[1]), "=r"(r[2]), "=r"(r[3]) : "r"(addr));
}
// FP8 e5m2 x e5m2 -> f16 accumulator (exact: acc is an even integer <= 4096)
__device__ __forceinline__ void qmma_f16(uint32_t* c, const uint32_t* a,
                                         uint32_t b0, uint32_t b1) {
    asm volatile(
        "mma.sync.aligned.m16n8k32.row.col.f16.e5m2.e5m2.f16 "
        "{%0,%1}, {%2,%3,%4,%5}, {%6,%7}, {%0,%1};"
        : "+r"(c[0]), "+r"(c[1])
        : "r"(a[0]), "r"(a[1]), "r"(a[2]), "r"(a[3]), "r"(b0), "r"(b1));
}

// ---------------- Unpack: 8 bits (LSB-first) -> 8 e5m2 (+/-1) + dense bit-pack ----
__device__ __forceinline__ uint2 unpack8(unsigned v) {
    uint2 r;
    r.x = 0xBCBCBCBCu ^ (((v >> 0) & 1u) << 7)
                      ^ (((v >> 1) & 1u) << 15)
                      ^ (((v >> 2) & 1u) << 23)
                      ^ (((v >> 3) & 1u) << 31);
    r.y = 0xBCBCBCBCu ^ (((v >> 4) & 1u) << 7)
                      ^ (((v >> 5) & 1u) << 15)
                      ^ (((v >> 6) & 1u) << 23)
                      ^ (((v >> 7) & 1u) << 31);
    return r;
}

#define NA4 (BATCH * PACKED_LEN / 4)   // 1048576
#define NW4 (OUTF * PACKED_LEN / 4)    // 524288
__global__ void unpack_all_kernel(const int* __restrict__ pa,
                                  const int* __restrict__ pw) {
    int i = blockIdx.x * blockDim.x + threadIdx.x;
    const int* __restrict__ src;
    uint4* __restrict__ dstf;
    uint32_t* __restrict__ dstp;
    int idx;
    if (i < NA4) { src = pa; dstf = (uint4*)g_A; dstp = g_Ap; idx = i; }
    else if (i < NA4 + NW4) { src = pw; dstf = (uint4*)g_W; dstp = g_Wp; idx = i - NA4; }
    else return;
    int4 p = ((const int4*)src)[idx];
    uint2 l0 = unpack8((unsigned)p.x);
    uint2 l1 = unpack8((unsigned)p.y);
    uint2 l2 = unpack8((unsigned)p.z);
    uint2 l3 = unpack8((unsigned)p.w);
    dstf[2 * idx]     = make_uint4(l0.x, l0.y, l1.x, l1.y);
    dstf[2 * idx + 1] = make_uint4(l2.x, l2.y, l3.x, l3.y);
    dstp[idx] = ((unsigned)p.x & 0xFFu)
              | (((unsigned)p.y & 0xFFu) << 8)
              | (((unsigned)p.z & 0xFFu) << 16)
              | (((unsigned)p.w & 0xFFu) << 24);
}

// ---------------- Hybrid GEMM (R11 structure: best measured config) ----------
__global__ __launch_bounds__(THREADS, 3)
void bitlinear_gemm(const float* __restrict__ bias, float* __restrict__ out) {
    extern __shared__ char smem_raw[];
    char* smem = (char*)(((uintptr_t)smem_raw + 1023) & ~(uintptr_t)1023);

    const int tid = threadIdx.x;
    const int bid = blockIdx.x;
    const int g   = bid >> 3;      // 0..511
    const int s   = bid & 7;       // 0..7; s==7 -> popc CTA

    // ================= POPC path (1 in 8 CTAs, uniformly interleaved) ========
    if (s == 7) {
        const int mtile = g >> 3;          // 0..63
        const int ntile = NQ + (g & 7);    // 56..63
        uint32_t* As = (uint32_t*)smem;    // [64 kw][128 rows] = 32 KB
        uint32_t* Ws = As + 64 * 128;      // [64 kw][64 cols]  = 16 KB

        const int rg  = tid & 15;          // -> rows rg*8 .. rg*8+7
        const int cg4 = (tid >> 4) * 4;    // -> cols cg4 .. cg4+3

        int acc[8][4];
#pragma unroll
        for (int r = 0; r < 8; ++r)
#pragma unroll
            for (int c = 0; c < 4; ++c) acc[r][c] = 0;

        const int arow  = tid & 127;
        const int ahalf = tid >> 7;
        const int wrow  = tid & 63;
        const int wq    = tid >> 6;

#pragma unroll 1
        for (int ch = 0; ch < 2; ++ch) {
            {
                const uint4* asrc = (const uint4*)(g_Ap
                    + (size_t)(mtile * TM + arow) * 128 + ch * 64 + ahalf * 32);
#pragma unroll
                for (int i = 0; i < 8; ++i) {
                    uint4 v = asrc[i];
                    int kwl = ahalf * 32 + i * 4;
                    As[(kwl + 0) * 128 + arow] = v.x;
                    As[(kwl + 1) * 128 + arow] = v.y;
                    As[(kwl + 2) * 128 + arow] = v.z;
                    As[(kwl + 3) * 128 + arow] = v.w;
                }
                const uint4* wsrc = (const uint4*)(g_Wp
                    + (size_t)(ntile * TN + wrow) * 128 + ch * 64 + wq * 16);
#pragma unroll
                for (int i = 0; i < 4; ++i) {
                    uint4 v = wsrc[i];
                    int kwl = wq * 16 + i * 4;
                    Ws[(kwl + 0) * 64 + wrow] = v.x;
                    Ws[(kwl + 1) * 64 + wrow] = v.y;
                    Ws[(kwl + 2) * 64 + wrow] = v.z;
                    Ws[(kwl + 3) * 64 + wrow] = v.w;
                }
            }
            __syncthreads();

            // kw processed in PAIRS: acc += popc(..kw..) + popc(..kw+1..)
            // -> ptxas emits IADD3, cutting one IADD per element-pair (~8% ALU).
#pragma unroll 1
            for (int kw = 0; kw < 64; kw += 2) {
                const uint4* As0 = (const uint4*)(As + kw * 128 + rg * 8);
                const uint4* As1 = (const uint4*)(As + (kw + 1) * 128 + rg * 8);
                uint4 a00 = As0[0], a01 = As0[1];
                uint4 a10 = As1[0], a11 = As1[1];
                uint4 w0  = *(const uint4*)(Ws + kw * 64 + cg4);
                uint4 w1  = *(const uint4*)(Ws + (kw + 1) * 64 + cg4);
                uint32_t av0[8] = {a00.x, a00.y, a00.z, a00.w, a01.x, a01.y, a01.z, a01.w};
                uint32_t av1[8] = {a10.x, a10.y, a10.z, a10.w, a11.x, a11.y, a11.z, a11.w};
                uint32_t wv0[4] = {w0.x, w0.y, w0.z, w0.w};
                uint32_t wv1[4] = {w1.x, w1.y, w1.z, w1.w};
#pragma unroll
                for (int r = 0; r < 8; ++r)
#pragma unroll
                    for (int c = 0; c < 4; ++c)
                        acc[r][c] += __popc(av0[r] ^ wv0[c]) + __popc(av1[r] ^ wv1[c]);
            }
            __syncthreads();
        }

        const int colbase = ntile * TN + cg4;
        float b0 = __ldg(bias + colbase + 0);
        float b1 = __ldg(bias + colbase + 1);
        float b2 = __ldg(bias + colbase + 2);
        float b3 = __ldg(bias + colbase + 3);
#pragma unroll
        for (int r = 0; r < 8; ++r) {
            int row = mtile * TM + rg * 8 + r;
            float4 o;
            o.x = (float)(4096 - 2 * acc[r][0]) + b0;
            o.y = (float)(4096 - 2 * acc[r][1]) + b1;
            o.z = (float)(4096 - 2 * acc[r][2]) + b2;
            o.w = (float)(4096 - 2 * acc[r][3]) + b3;
            *(float4*)(void*)(out + (size_t)row * OUTF + colbase) = o;
        }
        return;
    }

    // ================= QMMA path (7 in 8 CTAs) =================
    const int q = g * 7 + s;           // 0..3583
    const int mtile = q / NQ;          // 0..63
    const int ntile = q % NQ;          // 0..55

    const uint32_t sbase = smem_u32(smem);
    const int wid  = tid >> 5;
    const int lane = tid & 31;
    const int warp_m = wid & 3;
    const int warp_n = wid >> 2;

    const uint8_t* __restrict__ Ag0 = g_A + (size_t)(mtile * TM) * INF;
    const uint8_t* __restrict__ Wg0 = g_W + (size_t)(ntile * TN) * INF;

    const int tr = tid >> 3;
    const int tc = tid & 7;
    const uint8_t* pf_gA = Ag0 + (size_t)tr * INF + tc * 16;
    const uint8_t* pf_gW = Wg0 + (size_t)tr * INF + tc * 16;
    const uint32_t pf_s  = tr * 128 + ((tc ^ (tr & 7)) << 4);

    auto prefetch = [&](int kt) {
        const uint32_t sst = sbase + (kt % STAGES) * STAGE_BYTES;
        const uint8_t* ga = pf_gA + kt * KS;
        const uint8_t* gw = pf_gW + kt * KS;
#pragma unroll
        for (int it = 0; it < 4; ++it)
            cp_async16(sst + pf_s + it * (32 * 128), ga + (size_t)it * (32 * INF));
#pragma unroll
        for (int it = 0; it < 2; ++it)
            cp_async16(sst + A_TILE_BYTES + pf_s + it * (32 * 128),
                       gw + (size_t)it * (32 * INF));
        cp_commit();
    };

    const int j = lane >> 3;
    const int arow_in = (lane & 7) + ((j & 1) << 3);
    const int achk    = j >> 1;
    const int brow_in = (lane & 7) + ((j >> 1) << 3);
    const int bchk    = j & 1;

    uint32_t offA[2][4];
    uint32_t offB[2][4];
#pragma unroll
    for (int mf = 0; mf < 2; ++mf) {
        int row = warp_m * 32 + mf * 16 + arow_in;
#pragma unroll
        for (int ks = 0; ks < 4; ++ks)
            offA[mf][ks] = row * 128 + (((ks * 2 + achk) ^ (row & 7)) << 4);
    }
#pragma unroll
    for (int nb = 0; nb < 2; ++nb) {
        int row = warp_n * 32 + nb * 16 + brow_in;
#pragma unroll
        for (int ks = 0; ks < 4; ++ks)
            offB[nb][ks] = A_TILE_BYTES + row * 128 +
                           (((ks * 2 + bchk) ^ (row & 7)) << 4);
    }

    uint32_t c_acc[2][4][2];
#pragma unroll
    for (int mf = 0; mf < 2; ++mf)
#pragma unroll
        for (int nf = 0; nf < 4; ++nf) {
            c_acc[mf][nf][0] = 0u;
            c_acc[mf][nf][1] = 0u;
        }

    prefetch(0);
    prefetch(1);
    cp_wait<1>();
    __syncthreads();

    for (int kt = 0; kt < NK; ++kt) {
        const uint32_t sa = sbase + (kt % STAGES) * STAGE_BYTES;
        const bool notlast = (kt + 1 < NK);

#pragma unroll
        for (int ks = 0; ks < 4; ++ks) {
            uint32_t a[2][4], b[2][4];
#pragma unroll
            for (int mf = 0; mf < 2; ++mf) ldsm_x4(a[mf], sa + offA[mf][ks]);
#pragma unroll
            for (int nb = 0; nb < 2; ++nb) ldsm_x4(b[nb], sa + offB[nb][ks]);
#pragma unroll
            for (int mf = 0; mf < 2; ++mf)
#pragma unroll
                for (int nf = 0; nf < 4; ++nf)
                    qmma_f16(c_acc[mf][nf], a[mf],
                             b[nf >> 1][(nf & 1) * 2],
                             b[nf >> 1][(nf & 1) * 2 + 1]);

            if (ks == 2 && notlast) {
                cp_wait<0>();
                __syncthreads();
                if (kt + 2 < NK) prefetch(kt + 2);
            }
        }
    }

    // epilogue
    const int gid = lane >> 2;
    const int tig = lane & 3;
#pragma unroll
    for (int mf = 0; mf < 2; ++mf) {
        int r0 = mtile * TM + warp_m * 32 + mf * 16 + gid;
#pragma unroll
        for (int nf = 0; nf < 4; ++nf) {
            int col = ntile * TN + warp_n * 32 + nf * 8 + 2 * tig;
            float bx = __ldg(bias + col);
            float by = __ldg(bias + col + 1);
            half2 h0 = *(half2*)&c_acc[mf][nf][0];
            half2 h1 = *(half2*)&c_acc[mf][nf][1];
            float2 f0 = __half22float2(h0);
            float2 f1 = __half22float2(h1);
            float2 v0, v1;
            v0.x = f0.x + bx;  v0.y = f0.y + by;
            v1.x = f1.x + bx;  v1.y = f1.y + by;
            *(float2*)(void*)(out + (size_t)r0 * OUTF + col) = v0;
            *(float2*)(void*)(out + (size_t)(r0 + 8) * OUTF + col) = v1;
        }
    }
}

// ---------------- launch ----------------
extern "C" void kernel_launch(void* const* d_in, const int* in_sizes, int n_in,
                              void* d_out, int out_size) {
    const int*   inp  = (const int*)d_in[0];   // [8192, 512] int32 (low 8 bits)
    const int*   wp   = (const int*)d_in[1];   // [4096, 512] int32
    const float* bias = (const float*)d_in[2]; // [4096]
    float*       out  = (float*)d_out;         // [8192, 4096] fp32

    cudaFuncSetAttribute(bitlinear_gemm,
                         cudaFuncAttributeMaxDynamicSharedMemorySize, SMEM_DYN);

    const int nTot = NA4 + NW4;  // 1572864
    unpack_all_kernel<<<(nTot + 255) / 256, 256>>>(inp, wp);

    const int grid = (BATCH / TM) * (OUTF / TN);  // 4096
    bitlinear_gemm<<<grid, THREADS, SMEM_DYN>>>(bias, out);
}

// round 16
// speedup vs baseline: 1.1508x; 1.0655x over previous
#include <cuda_runtime.h>
#include <cuda_fp16.h>
#include <cstdint>

#define BATCH 8192
#define OUTF  4096
#define INF   4096
#define PACKED_LEN 512

// ---------------- GEMM tiling ----------------
#define TM 128
#define TN 64
#define KS 128                       // fp8 K elements per stage (128 B rows)
#define NK (INF / KS)                // 32 K-iterations
#define STAGES 3
#define THREADS 256

// Per 8 consecutive bids: 7 QMMA CTAs + 1 POPC CTA (uniform interleave).
// 512 groups: popc g -> (mtile=g>>3, ntile=56+(g&7)); qmma q=7g+s -> (q/56, q%56).
#define NPOPC 8
#define NQ    (64 - NPOPC)

#define A_TILE_BYTES (TM * 128)          // 16 KB
#define B_TILE_BYTES (TN * 128)          // 8 KB
#define STAGE_BYTES (A_TILE_BYTES + B_TILE_BYTES)  // 24 KB
#define SMEM_DYN (STAGES * STAGE_BYTES + 1024)     // ~73 KB -> 3 CTAs/SM

// Scratch (no cudaMalloc allowed -> __device__ globals)
__device__ __align__(16) uint8_t  g_A[(size_t)BATCH * INF];        // fp8, 32 MB
__device__ __align__(16) uint8_t  g_W[(size_t)OUTF * INF];         // fp8, 16 MB
__device__ __align__(16) uint32_t g_Ap[(size_t)BATCH * (INF/32)];  // packed, 4 MB
__device__ __align__(16) uint32_t g_Wp[(size_t)OUTF * (INF/32)];   // packed, 2 MB

// ---------------- helpers ----------------
__device__ __forceinline__ uint32_t smem_u32(const void* p) {
    return (uint32_t)__cvta_generic_to_shared(p);
}
__device__ __forceinline__ void cp_async16(uint32_t sdst, const void* gsrc) {
    asm volatile("cp.async.cg.shared.global [%0], [%1], 16;" :: "r"(sdst), "l"(gsrc));
}
__device__ __forceinline__ void cp_commit() {
    asm volatile("cp.async.commit_group;");
}
template <int N>
__device__ __forceinline__ void cp_wait() {
    asm volatile("cp.async.wait_group %0;" :: "n"(N));
}
__device__ __forceinline__ void ldsm_x4(uint32_t* r, uint32_t addr) {
    asm volatile("ldmatrix.sync.aligned.m8n8.x4.shared.b16 {%0,%1,%2,%3}, [%4];"
                 : "=r"(r[0]), "=r"(r[1]), "=r"(r[2]), "=r"(r[3]) : "r"(addr));
}
// FP8 e5m2 x e5m2 -> f16 accumulator (exact: acc is an even integer <= 4096)
__device__ __forceinline__ void qmma_f16(uint32_t* c, const uint32_t* a,
                                         uint32_t b0, uint32_t b1) {
    asm volatile(
        "mma.sync.aligned.m16n8k32.row.col.f16.e5m2.e5m2.f16 "
        "{%0,%1}, {%2,%3,%4,%5}, {%6,%7}, {%0,%1};"
        : "+r"(c[0]), "+r"(c[1])
        : "r"(a[0]), "r"(a[1]), "r"(a[2]), "r"(a[3]), "r"(b0), "r"(b1));
}

// ---------------- Unpack: 8 bits (LSB-first) -> 8 e5m2 (+/-1) + dense bit-pack ----
__device__ __forceinline__ uint2 unpack8(unsigned v) {
    uint2 r;
    r.x = 0xBCBCBCBCu ^ (((v >> 0) & 1u) << 7)
                      ^ (((v >> 1) & 1u) << 15)
                      ^ (((v >> 2) & 1u) << 23)
                      ^ (((v >> 3) & 1u) << 31);
    r.y = 0xBCBCBCBCu ^ (((v >> 4) & 1u) << 7)
                      ^ (((v >> 5) & 1u) << 15)
                      ^ (((v >> 6) & 1u) << 23)
                      ^ (((v >> 7) & 1u) << 31);
    return r;
}

#define NA4 (BATCH * PACKED_LEN / 4)   // 1048576
#define NW4 (OUTF * PACKED_LEN / 4)    // 524288
__global__ void unpack_all_kernel(const int* __restrict__ pa,
                                  const int* __restrict__ pw) {
    int i = blockIdx.x * blockDim.x + threadIdx.x;
    const int* src;
    uint4* dstf;
    uint32_t* dstp;
    int idx;
    if (i < NA4) { src = pa; dstf = (uint4*)g_A; dstp = g_Ap; idx = i; }
    else if (i < NA4 + NW4) { src = pw; dstf = (uint4*)g_W; dstp = g_Wp; idx = i - NA4; }
    else return;
    int4 p = ((const int4*)src)[idx];
    uint2 l0 = unpack8((unsigned)p.x);
    uint2 l1 = unpack8((unsigned)p.y);
    uint2 l2 = unpack8((unsigned)p.z);
    uint2 l3 = unpack8((unsigned)p.w);
    dstf[2 * idx]     = make_uint4(l0.x, l0.y, l1.x, l1.y);
    dstf[2 * idx + 1] = make_uint4(l2.x, l2.y, l3.x, l3.y);
    dstp[idx] = ((unsigned)p.x & 0xFFu)
              | (((unsigned)p.y & 0xFFu) << 8)
              | (((unsigned)p.z & 0xFFu) << 16)
              | (((unsigned)p.w & 0xFFu) << 24);
}

// ---------------- Hybrid GEMM ----------------
__global__ __launch_bounds__(THREADS, 3)
void bitlinear_gemm(const float* __restrict__ bias, float* __restrict__ out) {
    extern __shared__ char smem_raw[];
    char* smem = (char*)(((uintptr_t)smem_raw + 1023) & ~(uintptr_t)1023);

    const int tid = threadIdx.x;
    const int bid = blockIdx.x;
    const int g   = bid >> 3;      // 0..511
    const int s   = bid & 7;       // 0..7; s==7 -> popc CTA

    // ================= POPC path (1 in 8 CTAs, uniformly interleaved) ========
    if (s == 7) {
        const int mtile = g >> 3;          // 0..63
        const int ntile = NQ + (g & 7);    // 56..63
        uint32_t* As = (uint32_t*)smem;    // [64 kw][128 rows] = 32 KB
        uint32_t* Ws = As + 64 * 128;      // [64 kw][64 cols]  = 16 KB

        const int rg  = tid & 15;          // -> rows rg*8 .. rg*8+7 (consecutive)
        const int cg4 = (tid >> 4) * 4;    // -> cols cg4 .. cg4+3

        int acc[8][4];
#pragma unroll
        for (int r = 0; r < 8; ++r)
#pragma unroll
            for (int c = 0; c < 4; ++c) acc[r][c] = 0;

        const int arow  = tid & 127;       // loader row for A
        const int ahalf = tid >> 7;        // which 32-kw half
        const int wrow  = tid & 63;        // loader row for W
        const int wq    = tid >> 6;        // which 16-kw quarter

#pragma unroll 1
        for (int ch = 0; ch < 2; ++ch) {
            // cooperative load chunk ch (64 K-words) into kw-major (transposed) smem
            {
                const uint4* asrc = (const uint4*)(g_Ap
                    + (size_t)(mtile * TM + arow) * 128 + ch * 64 + ahalf * 32);
#pragma unroll
                for (int i = 0; i < 8; ++i) {
                    uint4 v = asrc[i];
                    int kwl = ahalf * 32 + i * 4;
                    As[(kwl + 0) * 128 + arow] = v.x;
                    As[(kwl + 1) * 128 + arow] = v.y;
                    As[(kwl + 2) * 128 + arow] = v.z;
                    As[(kwl + 3) * 128 + arow] = v.w;
                }
                const uint4* wsrc = (const uint4*)(g_Wp
                    + (size_t)(ntile * TN + wrow) * 128 + ch * 64 + wq * 16);
#pragma unroll
                for (int i = 0; i < 4; ++i) {
                    uint4 v = wsrc[i];
                    int kwl = wq * 16 + i * 4;
                    Ws[(kwl + 0) * 64 + wrow] = v.x;
                    Ws[(kwl + 1) * 64 + wrow] = v.y;
                    Ws[(kwl + 2) * 64 + wrow] = v.z;
                    Ws[(kwl + 3) * 64 + wrow] = v.w;
                }
            }
            __syncthreads();

#pragma unroll 2
            for (int kw = 0; kw < 64; ++kw) {
                // vectorized frags: 2x uint4 A (8 consecutive rows), 1x uint4 W
                const uint4* As4 = (const uint4*)(As + kw * 128 + rg * 8);
                uint4 a0 = As4[0];
                uint4 a1 = As4[1];
                uint4 w  = *(const uint4*)(Ws + kw * 64 + cg4);
                uint32_t av[8] = {a0.x, a0.y, a0.z, a0.w, a1.x, a1.y, a1.z, a1.w};
                uint32_t wv[4] = {w.x, w.y, w.z, w.w};
#pragma unroll
                for (int r = 0; r < 8; ++r)
#pragma unroll
                    for (int c = 0; c < 4; ++c)
                        acc[r][c] += __popc(av[r] ^ wv[c]);
            }
            __syncthreads();
        }

        // epilogue: dot = 4096 - 2*popcSum
        const int colbase = ntile * TN + cg4;
        float b0 = __ldg(bias + colbase + 0);
        float b1 = __ldg(bias + colbase + 1);
        float b2 = __ldg(bias + colbase + 2);
        float b3 = __ldg(bias + colbase + 3);
#pragma unroll
        for (int r = 0; r < 8; ++r) {
            int row = mtile * TM + rg * 8 + r;
            float4 o;
            o.x = (float)(4096 - 2 * acc[r][0]) + b0;
            o.y = (float)(4096 - 2 * acc[r][1]) + b1;
            o.z = (float)(4096 - 2 * acc[r][2]) + b2;
            o.w = (float)(4096 - 2 * acc[r][3]) + b3;
            *(float4*)(void*)(out + (size_t)row * OUTF + colbase) = o;
        }
        return;
    }

    // ================= QMMA path (7 in 8 CTAs) — R9 structure =================
    const int q = g * 7 + s;           // 0..3583
    const int mtile = q / NQ;          // 0..63
    const int ntile = q % NQ;          // 0..55

    const uint32_t sbase = smem_u32(smem);
    const int wid  = tid >> 5;
    const int lane = tid & 31;
    const int warp_m = wid & 3;    // 4 x 32 rows
    const int warp_n = wid >> 2;   // 2 x 32 cols

    const uint8_t* __restrict__ Ag0 = g_A + (size_t)(mtile * TM) * INF;
    const uint8_t* __restrict__ Wg0 = g_W + (size_t)(ntile * TN) * INF;

    const int tr = tid >> 3;
    const int tc = tid & 7;
    const uint8_t* pf_gA = Ag0 + (size_t)tr * INF + tc * 16;
    const uint8_t* pf_gW = Wg0 + (size_t)tr * INF + tc * 16;
    const uint32_t pf_s  = tr * 128 + ((tc ^ (tr & 7)) << 4);

    auto prefetch = [&](int kt) {
        const uint32_t sst = sbase + (kt % STAGES) * STAGE_BYTES;
        const uint8_t* ga = pf_gA + kt * KS;
        const uint8_t* gw = pf_gW + kt * KS;
#pragma unroll
        for (int it = 0; it < 4; ++it)
            cp_async16(sst + pf_s + it * (32 * 128), ga + (size_t)it * (32 * INF));
#pragma unroll
        for (int it = 0; it < 2; ++it)
            cp_async16(sst + A_TILE_BYTES + pf_s + it * (32 * 128),
                       gw + (size_t)it * (32 * INF));
        cp_commit();
    };

    const int j = lane >> 3;
    const int arow_in = (lane & 7) + ((j & 1) << 3);
    const int achk    = j >> 1;
    const int brow_in = (lane & 7) + ((j >> 1) << 3);
    const int bchk    = j & 1;

    uint32_t offA[2][4];
    uint32_t offB[2][4];
#pragma unroll
    for (int mf = 0; mf < 2; ++mf) {
        int row = warp_m * 32 + mf * 16 + arow_in;
#pragma unroll
        for (int ks = 0; ks < 4; ++ks)
            offA[mf][ks] = row * 128 + (((ks * 2 + achk) ^ (row & 7)) << 4);
    }
#pragma unroll
    for (int nb = 0; nb < 2; ++nb) {
        int row = warp_n * 32 + nb * 16 + brow_in;
#pragma unroll
        for (int ks = 0; ks < 4; ++ks)
            offB[nb][ks] = A_TILE_BYTES + row * 128 +
                           (((ks * 2 + bchk) ^ (row & 7)) << 4);
    }

    uint32_t c_acc[2][4][2];
#pragma unroll
    for (int mf = 0; mf < 2; ++mf)
#pragma unroll
        for (int nf = 0; nf < 4; ++nf) {
            c_acc[mf][nf][0] = 0u;
            c_acc[mf][nf][1] = 0u;
        }

    prefetch(0);
    prefetch(1);
    cp_wait<1>();
    __syncthreads();

    for (int kt = 0; kt < NK; ++kt) {
        const uint32_t sa = sbase + (kt % STAGES) * STAGE_BYTES;
        const bool notlast = (kt + 1 < NK);

#pragma unroll
        for (int ks = 0; ks < 4; ++ks) {
            uint32_t a[2][4], b[2][4];
#pragma unroll
            for (int mf = 0; mf < 2; ++mf) ldsm_x4(a[mf], sa + offA[mf][ks]);
#pragma unroll
            for (int nb = 0; nb < 2; ++nb) ldsm_x4(b[nb], sa + offB[nb][ks]);
#pragma unroll
            for (int mf = 0; mf < 2; ++mf)
#pragma unroll
                for (int nf = 0; nf < 4; ++nf)
                    qmma_f16(c_acc[mf][nf], a[mf],
                             b[nf >> 1][(nf & 1) * 2],
                             b[nf >> 1][(nf & 1) * 2 + 1]);

            if (ks == 2 && notlast) {
                cp_wait<0>();
                __syncthreads();
                if (kt + 2 < NK) prefetch(kt + 2);
            }
        }
    }

    // epilogue
    const int gid = lane >> 2;
    const int tig = lane & 3;
#pragma unroll
    for (int mf = 0; mf < 2; ++mf) {
        int r0 = mtile * TM + warp_m * 32 + mf * 16 + gid;
#pragma unroll
        for (int nf = 0; nf < 4; ++nf) {
            int col = ntile * TN + warp_n * 32 + nf * 8 + 2 * tig;
            float bx = __ldg(bias + col);
            float by = __ldg(bias + col + 1);
            half2 h0 = *(half2*)&c_acc[mf][nf][0];
            half2 h1 = *(half2*)&c_acc[mf][nf][1];
            float2 f0 = __half22float2(h0);
            float2 f1 = __half22float2(h1);
            float2 v0, v1;
            v0.x = f0.x + bx;  v0.y = f0.y + by;
            v1.x = f1.x + bx;  v1.y = f1.y + by;
            *(float2*)(void*)(out + (size_t)r0 * OUTF + col) = v0;
            *(float2*)(void*)(out + (size_t)(r0 + 8) * OUTF + col) = v1;
        }
    }
}

// ---------------- launch ----------------
extern "C" void kernel_launch(void* const* d_in, const int* in_sizes, int n_in,
                              void* d_out, int out_size) {
    const int*   inp  = (const int*)d_in[0];   // [8192, 512] int32 (low 8 bits)
    const int*   wp   = (const int*)d_in[1];   // [4096, 512] int32
    const float* bias = (const float*)d_in[2]; // [4096]
    float*       out  = (float*)d_out;         // [8192, 4096] fp32

    cudaFuncSetAttribute(bitlinear_gemm,
                         cudaFuncAttributeMaxDynamicSharedMemorySize, SMEM_DYN);

    const int nTot = NA4 + NW4;  // 1572864
    unpack_all_kernel<<<(nTot + 255) / 256, 256>>>(inp, wp);

    const int grid = (BATCH / TM) * (OUTF / TN);  // 4096
    bitlinear_gemm<<<grid, THREADS, SMEM_DYN>>>(bias, out);
}

// round 17
// speedup vs baseline: 1.1511x; 1.0003x over previous
#include <cuda_runtime.h>
#include <cuda_fp16.h>
#include <cstdint>

#define BATCH 8192
#define OUTF  4096
#define INF   4096
#define PACKED_LEN 512

// ---------------- GEMM tiling ----------------
#define TM 128
#define TN 64
#define KS 128                       // fp8 K elements per stage (128 B rows)
#define NK (INF / KS)                // 32 K-iterations
#define STAGES 3
#define THREADS 256

// Per 8 consecutive bids: 7 QMMA CTAs + 1 POPC CTA (uniform interleave).
// 512 groups: popc g -> (mtile=g>>3, ntile=56+(g&7)); qmma q=7g+s -> (q/56, q%56).
#define NPOPC 8
#define NQ    (64 - NPOPC)

#define A_TILE_BYTES (TM * 128)          // 16 KB
#define B_TILE_BYTES (TN * 128)          // 8 KB
#define STAGE_BYTES (A_TILE_BYTES + B_TILE_BYTES)  // 24 KB
#define SMEM_DYN (STAGES * STAGE_BYTES + 1024)     // ~73 KB -> 3 CTAs/SM

// Scratch (no cudaMalloc allowed -> __device__ globals)
__device__ __align__(16) uint8_t  g_A[(size_t)BATCH * INF];        // fp8, 32 MB
__device__ __align__(16) uint8_t  g_W[(size_t)OUTF * INF];         // fp8, 16 MB
__device__ __align__(16) uint32_t g_Ap[(size_t)BATCH * (INF/32)];  // packed, 4 MB
__device__ __align__(16) uint32_t g_Wp[(size_t)OUTF * (INF/32)];   // packed, 2 MB

// ---------------- helpers ----------------
__device__ __forceinline__ uint32_t smem_u32(const void* p) {
    return (uint32_t)__cvta_generic_to_shared(p);
}
__device__ __forceinline__ void cp_async16(uint32_t sdst, const void* gsrc) {
    asm volatile("cp.async.cg.shared.global [%0], [%1], 16;" :: "r"(sdst), "l"(gsrc));
}
__device__ __forceinline__ void cp_commit() {
    asm volatile("cp.async.commit_group;");
}
template <int N>
__device__ __forceinline__ void cp_wait() {
    asm volatile("cp.async.wait_group %0;" :: "n"(N));
}
__device__ __forceinline__ void ldsm_x4(uint32_t* r, uint32_t addr) {
    asm volatile("ldmatrix.sync.aligned.m8n8.x4.shared.b16 {%0,%1,%2,%3}, [%4];"
                 : "=r"(r[0]), "=r"(r[1]), "=r"(r[2]), "=r"(r[3]) : "r"(addr));
}
// FP8 e5m2 x e5m2 -> f16 accumulator (exact: acc is an even integer <= 4096)
__device__ __forceinline__ void qmma_f16(uint32_t* c, const uint32_t* a,
                                         uint32_t b0, uint32_t b1) {
    asm volatile(
        "mma.sync.aligned.m16n8k32.row.col.f16.e5m2.e5m2.f16 "
        "{%0,%1}, {%2,%3,%4,%5}, {%6,%7}, {%0,%1};"
        : "+r"(c[0]), "+r"(c[1])
        : "r"(a[0]), "r"(a[1]), "r"(a[2]), "r"(a[3]), "r"(b0), "r"(b1));
}

// ---------------- Unpack: 8 bits (LSB-first) -> 8 e5m2 (+/-1) + dense bit-pack ----
__device__ __forceinline__ uint2 unpack8(unsigned v) {
    uint2 r;
    r.x = 0xBCBCBCBCu ^ (((v >> 0) & 1u) << 7)
                      ^ (((v >> 1) & 1u) << 15)
                      ^ (((v >> 2) & 1u) << 23)
                      ^ (((v >> 3) & 1u) << 31);
    r.y = 0xBCBCBCBCu ^ (((v >> 4) & 1u) << 7)
                      ^ (((v >> 5) & 1u) << 15)
                      ^ (((v >> 6) & 1u) << 23)
                      ^ (((v >> 7) & 1u) << 31);
    return r;
}

#define NA4 (BATCH * PACKED_LEN / 4)   // 1048576
#define NW4 (OUTF * PACKED_LEN / 4)    // 524288
__global__ void unpack_all_kernel(const int* __restrict__ pa,
                                  const int* __restrict__ pw) {
    int i = blockIdx.x * blockDim.x + threadIdx.x;
    const int* src;
    uint4* dstf;
    uint32_t* dstp;
    int idx;
    if (i < NA4) { src = pa; dstf = (uint4*)g_A; dstp = g_Ap; idx = i; }
    else if (i < NA4 + NW4) { src = pw; dstf = (uint4*)g_W; dstp = g_Wp; idx = i - NA4; }
    else return;
    int4 p = ((const int4*)src)[idx];
    uint2 l0 = unpack8((unsigned)p.x);
    uint2 l1 = unpack8((unsigned)p.y);
    uint2 l2 = unpack8((unsigned)p.z);
    uint2 l3 = unpack8((unsigned)p.w);
    dstf[2 * idx]     = make_uint4(l0.x, l0.y, l1.x, l1.y);
    dstf[2 * idx + 1] = make_uint4(l2.x, l2.y, l3.x, l3.y);
    dstp[idx] = ((unsigned)p.x & 0xFFu)
              | (((unsigned)p.y & 0xFFu) << 8)
              | (((unsigned)p.z & 0xFFu) << 16)
              | (((unsigned)p.w & 0xFFu) << 24);
}

// ---------------- Hybrid GEMM ----------------
__global__ __launch_bounds__(THREADS, 3)
void bitlinear_gemm(const float* __restrict__ bias, float* __restrict__ out) {
    extern __shared__ char smem_raw[];
    char* smem = (char*)(((uintptr_t)smem_raw + 1023) & ~(uintptr_t)1023);

    const int tid = threadIdx.x;
    const int bid = blockIdx.x;
    const int g   = bid >> 3;      // 0..511
    const int s   = bid & 7;       // 0..7; s==7 -> popc CTA

    // ================= POPC path (1 in 8 CTAs, uniformly interleaved) ========
    if (s == 7) {
        const int mtile = g >> 3;          // 0..63
        const int ntile = NQ + (g & 7);    // 56..63
        uint32_t* As = (uint32_t*)smem;    // [64 kw][128 rows] = 32 KB
        uint32_t* Ws = As + 64 * 128;      // [64 kw][64 cols]  = 16 KB

        const int rg  = tid & 15;          // -> rows rg*8 .. rg*8+7 (consecutive)
        const int cg4 = (tid >> 4) * 4;    // -> cols cg4 .. cg4+3

        int acc[8][4];
#pragma unroll
        for (int r = 0; r < 8; ++r)
#pragma unroll
            for (int c = 0; c < 4; ++c) acc[r][c] = 0;

        const int arow  = tid & 127;       // loader row for A
        const int ahalf = tid >> 7;        // which 32-kw half
        const int wrow  = tid & 63;        // loader row for W
        const int wq    = tid >> 6;        // which 16-kw quarter

#pragma unroll 1
        for (int ch = 0; ch < 2; ++ch) {
            // cooperative load chunk ch (64 K-words) into kw-major (transposed) smem
            {
                const uint4* asrc = (const uint4*)(g_Ap
                    + (size_t)(mtile * TM + arow) * 128 + ch * 64 + ahalf * 32);
#pragma unroll
                for (int i = 0; i < 8; ++i) {
                    uint4 v = asrc[i];
                    int kwl = ahalf * 32 + i * 4;
                    As[(kwl + 0) * 128 + arow] = v.x;
                    As[(kwl + 1) * 128 + arow] = v.y;
                    As[(kwl + 2) * 128 + arow] = v.z;
                    As[(kwl + 3) * 128 + arow] = v.w;
                }
                const uint4* wsrc = (const uint4*)(g_Wp
                    + (size_t)(ntile * TN + wrow) * 128 + ch * 64 + wq * 16);
#pragma unroll
                for (int i = 0; i < 4; ++i) {
                    uint4 v = wsrc[i];
                    int kwl = wq * 16 + i * 4;
                    Ws[(kwl + 0) * 64 + wrow] = v.x;
                    Ws[(kwl + 1) * 64 + wrow] = v.y;
                    Ws[(kwl + 2) * 64 + wrow] = v.z;
                    Ws[(kwl + 3) * 64 + wrow] = v.w;
                }
            }
            __syncthreads();

            // SINGLE-VARIABLE PROBE vs R16: unroll 2 -> 4 (deeper independent
            // LDS->POPC chains; popc tile finishes sooner, shrinking its
            // issue-slot interference window with co-resident QMMA CTAs).
#pragma unroll 4
            for (int kw = 0; kw < 64; ++kw) {
                // vectorized frags: 2x uint4 A (8 consecutive rows), 1x uint4 W
                const uint4* As4 = (const uint4*)(As + kw * 128 + rg * 8);
                uint4 a0 = As4[0];
                uint4 a1 = As4[1];
                uint4 w  = *(const uint4*)(Ws + kw * 64 + cg4);
                uint32_t av[8] = {a0.x, a0.y, a0.z, a0.w, a1.x, a1.y, a1.z, a1.w};
                uint32_t wv[4] = {w.x, w.y, w.z, w.w};
#pragma unroll
                for (int r = 0; r < 8; ++r)
#pragma unroll
                    for (int c = 0; c < 4; ++c)
                        acc[r][c] += __popc(av[r] ^ wv[c]);
            }
            __syncthreads();
        }

        // epilogue: dot = 4096 - 2*popcSum
        const int colbase = ntile * TN + cg4;
        float b0 = __ldg(bias + colbase + 0);
        float b1 = __ldg(bias + colbase + 1);
        float b2 = __ldg(bias + colbase + 2);
        float b3 = __ldg(bias + colbase + 3);
#pragma unroll
        for (int r = 0; r < 8; ++r) {
            int row = mtile * TM + rg * 8 + r;
            float4 o;
            o.x = (float)(4096 - 2 * acc[r][0]) + b0;
            o.y = (float)(4096 - 2 * acc[r][1]) + b1;
            o.z = (float)(4096 - 2 * acc[r][2]) + b2;
            o.w = (float)(4096 - 2 * acc[r][3]) + b3;
            *(float4*)(void*)(out + (size_t)row * OUTF + colbase) = o;
        }
        return;
    }

    // ================= QMMA path (7 in 8 CTAs) — R9 structure =================
    const int q = g * 7 + s;           // 0..3583
    const int mtile = q / NQ;          // 0..63
    const int ntile = q % NQ;          // 0..55

    const uint32_t sbase = smem_u32(smem);
    const int wid  = tid >> 5;
    const int lane = tid & 31;
    const int warp_m = wid & 3;    // 4 x 32 rows
    const int warp_n = wid >> 2;   // 2 x 32 cols

    const uint8_t* __restrict__ Ag0 = g_A + (size_t)(mtile * TM) * INF;
    const uint8_t* __restrict__ Wg0 = g_W + (size_t)(ntile * TN) * INF;

    const int tr = tid >> 3;
    const int tc = tid & 7;
    const uint8_t* pf_gA = Ag0 + (size_t)tr * INF + tc * 16;
    const uint8_t* pf_gW = Wg0 + (size_t)tr * INF + tc * 16;
    const uint32_t pf_s  = tr * 128 + ((tc ^ (tr & 7)) << 4);

    auto prefetch = [&](int kt) {
        const uint32_t sst = sbase + (kt % STAGES) * STAGE_BYTES;
        const uint8_t* ga = pf_gA + kt * KS;
        const uint8_t* gw = pf_gW + kt * KS;
#pragma unroll
        for (int it = 0; it < 4; ++it)
            cp_async16(sst + pf_s + it * (32 * 128), ga + (size_t)it * (32 * INF));
#pragma unroll
        for (int it = 0; it < 2; ++it)
            cp_async16(sst + A_TILE_BYTES + pf_s + it * (32 * 128),
                       gw + (size_t)it * (32 * INF));
        cp_commit();
    };

    const int j = lane >> 3;
    const int arow_in = (lane & 7) + ((j & 1) << 3);
    const int achk    = j >> 1;
    const int brow_in = (lane & 7) + ((j >> 1) << 3);
    const int bchk    = j & 1;

    uint32_t offA[2][4];
    uint32_t offB[2][4];
#pragma unroll
    for (int mf = 0; mf < 2; ++mf) {
        int row = warp_m * 32 + mf * 16 + arow_in;
#pragma unroll
        for (int ks = 0; ks < 4; ++ks)
            offA[mf][ks] = row * 128 + (((ks * 2 + achk) ^ (row & 7)) << 4);
    }
#pragma unroll
    for (int nb = 0; nb < 2; ++nb) {
        int row = warp_n * 32 + nb * 16 + brow_in;
#pragma unroll
        for (int ks = 0; ks < 4; ++ks)
            offB[nb][ks] = A_TILE_BYTES + row * 128 +
                           (((ks * 2 + bchk) ^ (row & 7)) << 4);
    }

    uint32_t c_acc[2][4][2];
#pragma unroll
    for (int mf = 0; mf < 2; ++mf)
#pragma unroll
        for (int nf = 0; nf < 4; ++nf) {
            c_acc[mf][nf][0] = 0u;
            c_acc[mf][nf][1] = 0u;
        }

    prefetch(0);
    prefetch(1);
    cp_wait<1>();
    __syncthreads();

    for (int kt = 0; kt < NK; ++kt) {
        const uint32_t sa = sbase + (kt % STAGES) * STAGE_BYTES;
        const bool notlast = (kt + 1 < NK);

#pragma unroll
        for (int ks = 0; ks < 4; ++ks) {
            uint32_t a[2][4], b[2][4];
#pragma unroll
            for (int mf = 0; mf < 2; ++mf) ldsm_x4(a[mf], sa + offA[mf][ks]);
#pragma unroll
            for (int nb = 0; nb < 2; ++nb) ldsm_x4(b[nb], sa + offB[nb][ks]);
#pragma unroll
            for (int mf = 0; mf < 2; ++mf)
#pragma unroll
                for (int nf = 0; nf < 4; ++nf)
                    qmma_f16(c_acc[mf][nf], a[mf],
                             b[nf >> 1][(nf & 1) * 2],
                             b[nf >> 1][(nf & 1) * 2 + 1]);

            if (ks == 2 && notlast) {
                cp_wait<0>();
                __syncthreads();
                if (kt + 2 < NK) prefetch(kt + 2);
            }
        }
    }

    // epilogue
    const int gid = lane >> 2;
    const int tig = lane & 3;
#pragma unroll
    for (int mf = 0; mf < 2; ++mf) {
        int r0 = mtile * TM + warp_m * 32 + mf * 16 + gid;
#pragma unroll
        for (int nf = 0; nf < 4; ++nf) {
            int col = ntile * TN + warp_n * 32 + nf * 8 + 2 * tig;
            float bx = __ldg(bias + col);
            float by = __ldg(bias + col + 1);
            half2 h0 = *(half2*)&c_acc[mf][nf][0];
            half2 h1 = *(half2*)&c_acc[mf][nf][1];
            float2 f0 = __half22float2(h0);
            float2 f1 = __half22float2(h1);
            float2 v0, v1;
            v0.x = f0.x + bx;  v0.y = f0.y + by;
            v1.x = f1.x + bx;  v1.y = f1.y + by;
            *(float2*)(void*)(out + (size_t)r0 * OUTF + col) = v0;
            *(float2*)(void*)(out + (size_t)(r0 + 8) * OUTF + col) = v1;
        }
    }
}

// ---------------- launch ----------------
extern "C" void kernel_launch(void* const* d_in, const int* in_sizes, int n_in,
                              void* d_out, int out_size) {
    const int*   inp  = (const int*)d_in[0];   // [8192, 512] int32 (low 8 bits)
    const int*   wp   = (const int*)d_in[1];   // [4096, 512] int32
    const float* bias = (const float*)d_in[2]; // [4096]
    float*       out  = (float*)d_out;         // [8192, 4096] fp32

    cudaFuncSetAttribute(bitlinear_gemm,
                         cudaFuncAttributeMaxDynamicSharedMemorySize, SMEM_DYN);

    const int nTot = NA4 + NW4;  // 1572864
    unpack_all_kernel<<<(nTot + 255) / 256, 256>>>(inp, wp);

    const int grid = (BATCH / TM) * (OUTF / TN);  // 4096
    bitlinear_gemm<<<grid, THREADS, SMEM_DYN>>>(bias, out);
}